// round 12
// baseline (speedup 1.0000x reference)
#include <cuda_runtime.h>
#include <cstdint>

#define NN 100000
#define EE 3200000
#define IN_CH 256
#define HID 64
#define OUTC 32

#define SCAN_B 1024
#define NBLK ((NN + SCAN_B - 1) / SCAN_B)   // 98

#define HIST_BLOCKS 3125                    // 3125*128*8 == EE exactly
#define GEMM_BLOCKS ((NN + 127) / 128)      // 782

// ---------------- scratch (no allocations allowed) ----------------
__device__ int   d_is64;                      // 1 if edge_index is int64, else 0
__device__ __align__(16) int   d_cnt[NN];     // in-degree (edges only)
__device__ __align__(16) int   d_off[NN];     // CSR start offsets
__device__ __align__(16) int   d_cur[NN];     // fill cursors
__device__ __align__(16) int   d_erow[EE];    // CSR payload: source node per edge
__device__ __align__(16) int   d_bsum[NBLK];  // per-block count sums
__device__ __align__(16) int   d_boff[NBLK];  // scanned block offsets
__device__ __align__(16) float d_dis[NN];
__device__ __align__(16) float d_g1[(size_t)NN * HID];    // UNSCALED x @ W1
__device__ __align__(16) float d_g2[(size_t)NN * OUTC];   // scaled: dis * (h1 @ W2)

// ---------------- packed fp32x2 helpers (sm_100+: FFMA2) ----------------
__device__ __forceinline__ unsigned long long pack2(float x, float y) {
    unsigned long long r;
    asm("mov.b64 %0, {%1, %2};" : "=l"(r) : "f"(x), "f"(y));
    return r;
}
__device__ __forceinline__ unsigned long long fma2(unsigned long long a,
                                                   unsigned long long b,
                                                   unsigned long long c) {
    unsigned long long d;
    asm("fma.rn.f32x2 %0, %1, %2, %3;" : "=l"(d) : "l"(a), "l"(b), "l"(c));
    return d;
}
__device__ __forceinline__ void unpack2(unsigned long long v, float& x, float& y) {
    asm("mov.b64 {%0, %1}, %2;" : "=f"(x), "=f"(y) : "l"(v));
}

// ---------------- dtype detector: int64 edge_index has all-zero odd words ----------------
__global__ void k_detect(const int* __restrict__ ei_w) {
    int lane = threadIdx.x;  // one warp
    int nz = 0;
#pragma unroll
    for (int j = 0; j < 8; j++) {
        long long k = (long long)(lane * 8 + j) * (EE / 512);  // < EE/2
        nz |= ei_w[2 * k + 1];
    }
    unsigned any = __ballot_sync(0xffffffffu, nz != 0);
    if (lane == 0) d_is64 = (any == 0u) ? 1 : 0;
}

// ---------------- zero histogram ----------------
__global__ void k_zero() {
    unsigned i = blockIdx.x * blockDim.x + threadIdx.x;
    if (i < (unsigned)NN) d_cnt[i] = 0;
}

// ---------------- FUSED: histogram (blocks [0,HIST_BLOCKS)) + GEMM1 (rest) ----------------
// g1 = x @ W1 (UNSCALED; dis applied in agg1). Histogram counts targets.
__global__ __launch_bounds__(128) void k_gemm1_hist(const float* __restrict__ x,
                                                    const float* __restrict__ W1,
                                                    const void* __restrict__ ei) {
    __shared__ float As[128][33];
    __shared__ float Bs[32][64];

    if (blockIdx.x < HIST_BLOCKS) {
        // ---- histogram role: 8 edges per thread, grid-stride ----
        const unsigned stride = HIST_BLOCKS * 128;
        unsigned e = blockIdx.x * 128 + threadIdx.x;
        if (d_is64) {
            const long long* p = (const long long*)ei + EE;  // col stream
#pragma unroll
            for (int it = 0; it < 8; it++, e += stride)
                atomicAdd(&d_cnt[(int)p[e]], 1);
        } else {
            const int* p = (const int*)ei + EE;
#pragma unroll
            for (int it = 0; it < 8; it++, e += stride)
                atomicAdd(&d_cnt[p[e]], 1);
        }
        return;
    }

    // ---- GEMM role ----
    int t = threadIdx.x;
    int m0 = (blockIdx.x - HIST_BLOCKS) * 128;
    int ty = t >> 3;          // 0..15
    int tx = t & 7;           // 0..7
    unsigned long long acc[8][4];
    const unsigned long long z = pack2(0.f, 0.f);
#pragma unroll
    for (int i = 0; i < 8; i++)
#pragma unroll
        for (int j = 0; j < 4; j++) acc[i][j] = z;

    for (int k0 = 0; k0 < IN_CH; k0 += 32) {
#pragma unroll
        for (int jj = 0; jj < 4; jj++) {
            int m = jj * 32 + (t >> 2);
            int kq = (t & 3) * 8;
            int gm = m0 + m;
            float4 v0, v1;
            if (gm < NN) {
                const float* src = x + (size_t)gm * IN_CH + k0 + kq;
                v0 = *(const float4*)src;
                v1 = *(const float4*)(src + 4);
            } else {
                v0 = make_float4(0.f, 0.f, 0.f, 0.f);
                v1 = v0;
            }
            As[m][kq + 0] = v0.x; As[m][kq + 1] = v0.y;
            As[m][kq + 2] = v0.z; As[m][kq + 3] = v0.w;
            As[m][kq + 4] = v1.x; As[m][kq + 5] = v1.y;
            As[m][kq + 6] = v1.z; As[m][kq + 7] = v1.w;
        }
#pragma unroll
        for (int jj = 0; jj < 4; jj++) {
            int idx = t + jj * 128;
            int k = idx >> 4;
            int q = (idx & 15) * 4;
            float4 w = *(const float4*)(W1 + (size_t)(k0 + k) * HID + q);
            Bs[k][q + 0] = w.x; Bs[k][q + 1] = w.y;
            Bs[k][q + 2] = w.z; Bs[k][q + 3] = w.w;
        }
        __syncthreads();
#pragma unroll
        for (int k = 0; k < 32; k++) {
            unsigned long long a2[8], b2[4];
#pragma unroll
            for (int i = 0; i < 8; i++) {
                float a = As[ty * 8 + i][k];
                a2[i] = pack2(a, a);
            }
#pragma unroll
            for (int j = 0; j < 4; j++) {
                float2 b = *(const float2*)&Bs[k][tx * 8 + j * 2];
                b2[j] = pack2(b.x, b.y);
            }
#pragma unroll
            for (int i = 0; i < 8; i++)
#pragma unroll
                for (int j = 0; j < 4; j++) acc[i][j] = fma2(a2[i], b2[j], acc[i][j]);
        }
        __syncthreads();
    }
#pragma unroll
    for (int i = 0; i < 8; i++) {
        int m = m0 + ty * 8 + i;
        if (m < NN) {
            float r[8];
#pragma unroll
            for (int j = 0; j < 4; j++) unpack2(acc[i][j], r[j * 2], r[j * 2 + 1]);
            float4 v0 = make_float4(r[0], r[1], r[2], r[3]);
            float4 v1 = make_float4(r[4], r[5], r[6], r[7]);
            *(float4*)&d_g1[(size_t)m * HID + tx * 8] = v0;
            *(float4*)&d_g1[(size_t)m * HID + tx * 8 + 4] = v1;
        }
    }
}

// ---------------- scan phase 1: per-block sums ----------------
__global__ __launch_bounds__(SCAN_B) void k_bsum() {
    __shared__ int sred[SCAN_B / 32];
    int t = threadIdx.x;
    unsigned i = blockIdx.x * SCAN_B + t;
    int c = (i < (unsigned)NN) ? d_cnt[i] : 0;
    int w = c;
#pragma unroll
    for (int off = 16; off; off >>= 1) w += __shfl_xor_sync(0xffffffffu, w, off);
    if ((t & 31) == 0) sred[t >> 5] = w;
    __syncthreads();
    if (t < 32) {
        int s = (t < SCAN_B / 32) ? sred[t] : 0;
#pragma unroll
        for (int off = 16; off; off >>= 1) s += __shfl_xor_sync(0xffffffffu, s, off);
        if (t == 0) d_bsum[blockIdx.x] = s;
    }
}

// ---------------- scan phase 2: exclusive scan of 98 block sums ----------------
__global__ void k_bscan() {
    __shared__ int sv[128];
    int t = threadIdx.x;  // 128 threads
    sv[t] = (t < NBLK) ? d_bsum[t] : 0;
    __syncthreads();
#pragma unroll
    for (int off = 1; off < 128; off <<= 1) {
        int v = (t >= off) ? sv[t - off] : 0;
        __syncthreads();
        sv[t] += v;
        __syncthreads();
    }
    if (t < NBLK) d_boff[t] = (t == 0) ? 0 : sv[t - 1];
}

// ---------------- scan phase 3: intra-block exclusive scan + finalize ----------------
__global__ __launch_bounds__(SCAN_B) void k_off() {
    __shared__ int swsum[SCAN_B / 32];
    int t = threadIdx.x;
    int lane = t & 31;
    int wp = t >> 5;
    unsigned i = blockIdx.x * SCAN_B + t;
    int c = (i < (unsigned)NN) ? d_cnt[i] : 0;
    int s = c;
#pragma unroll
    for (int off = 1; off < 32; off <<= 1) {
        int v = __shfl_up_sync(0xffffffffu, s, off);
        if (lane >= off) s += v;
    }
    if (lane == 31) swsum[wp] = s;
    __syncthreads();
    if (t < 32) {
        int ws = (t < SCAN_B / 32) ? swsum[t] : 0;
#pragma unroll
        for (int off = 1; off < 32; off <<= 1) {
            int v = __shfl_up_sync(0xffffffffu, ws, off);
            if ((t & 31) >= off) ws += v;
        }
        if (t < SCAN_B / 32) swsum[t] = ws;
    }
    __syncthreads();
    int excl = s - c + (wp ? swsum[wp - 1] : 0) + d_boff[blockIdx.x];
    if (i < (unsigned)NN) {
        d_off[i] = excl;
        d_cur[i] = excl;
        d_dis[i] = rsqrtf((float)(c + 1));  // +1 self loop
    }
}

// ---------------- fill CSR, 4 edges per thread (MLP) ----------------
__global__ void k_fill(const void* __restrict__ ei) {
    unsigned e0 = (blockIdx.x * blockDim.x + threadIdx.x) * 4u;
    if (e0 >= (unsigned)EE) return;  // EE divisible by 4: all full quads
    int r[4], c[4];
    if (d_is64) {
        const long long* p = (const long long*)ei;
#pragma unroll
        for (int u = 0; u < 4; u++) {
            r[u] = (int)p[e0 + u];
            c[u] = (int)p[(size_t)EE + e0 + u];
        }
    } else {
        const int* p = (const int*)ei;
#pragma unroll
        for (int u = 0; u < 4; u++) {
            r[u] = p[e0 + u];
            c[u] = p[EE + e0 + u];
        }
    }
#pragma unroll
    for (int u = 0; u < 4; u++) {
        int pos = atomicAdd(&d_cur[c[u]], 1);
        d_erow[pos] = r[u];
    }
}

// ---------------- agg1 fused: gather dis[r]*g1[r] + self + ELU + GEMM2 -> g2 ----------------
// 1 warp per node; lane owns features 2*lane, 2*lane+1. W2 in shared.
__global__ __launch_bounds__(256) void k_agg1(const float* __restrict__ b1,
                                              const float* __restrict__ W2) {
    __shared__ float sW[64][32];   // W2
    __shared__ float sh[8][64];    // h per warp
    int t = threadIdx.x;
    int warp = t >> 5;
    int lane = t & 31;
    ((float4*)sW)[t] = ((const float4*)W2)[t];
    ((float4*)sW)[t + 256] = ((const float4*)W2)[t + 256];
    __syncthreads();

    int v = blockIdx.x * 8 + warp;
    if (v >= NN) return;

    int start = d_off[v];
    int cnt = d_cnt[v];
    float s = d_dis[v];
    // self term: dis[v] * g1[v]
    float2 g0 = *(const float2*)(d_g1 + (size_t)v * HID + lane * 2);
    float2 acc = make_float2(s * g0.x, s * g0.y);

    for (int base = 0; base < cnt; base += 32) {
        int nb = cnt - base; if (nb > 32) nb = 32;
        int er = (lane < nb) ? d_erow[start + base + lane] : 0;
        int nb8 = (nb + 7) & ~7;
        for (int j = 0; j < nb8; j += 8) {
            float2 g[8];
            float dr[8];
#pragma unroll
            for (int u = 0; u < 8; u++) {
                int jj = j + u;
                int r = __shfl_sync(0xffffffffu, er, jj & 31);
                bool pv = jj < nb;
                r = pv ? r : v;                       // in-range dummy
                dr[u] = pv ? d_dis[r] : 0.f;          // dr=0 kills dummy contribution
                g[u] = *(const float2*)(d_g1 + (size_t)r * HID + lane * 2);
            }
#pragma unroll
            for (int u = 0; u < 8; u++) {
                acc.x = fmaf(dr[u], g[u].x, acc.x);
                acc.y = fmaf(dr[u], g[u].y, acc.y);
            }
        }
    }

    float p0 = s * acc.x + b1[lane * 2];
    float p1 = s * acc.y + b1[lane * 2 + 1];
    float h0 = p0 > 0.f ? p0 : expm1f(p0);
    float h1 = p1 > 0.f ? p1 : expm1f(p1);
    sh[warp][lane * 2] = h0;
    sh[warp][lane * 2 + 1] = h1;
    __syncwarp();

    // GEMM2 for this node: out[o=lane] = sum_f h[f] * W2[f][o]
    float o_acc = 0.f;
#pragma unroll
    for (int f = 0; f < 64; f++) o_acc = fmaf(sh[warp][f], sW[f][lane], o_acc);
    d_g2[(size_t)v * OUTC + lane] = s * o_acc;   // g2 stored SCALED
}

// ---------------- agg2 fused: gather g2 + self + ELU + dot(Wc) -> out ----------------
__global__ __launch_bounds__(256) void k_agg2(const float* __restrict__ b2,
                                              const float* __restrict__ Wc,
                                              const float* __restrict__ bc,
                                              float* __restrict__ out) {
    int t = threadIdx.x;
    int warp = t >> 5;
    int lane = t & 31;
    int v = blockIdx.x * 8 + warp;
    if (v >= NN) return;

    int start = d_off[v];
    int cnt = d_cnt[v];
    float acc = d_g2[(size_t)v * OUTC + lane];  // self (g2 already scaled)

    for (int base = 0; base < cnt; base += 32) {
        int nb = cnt - base; if (nb > 32) nb = 32;
        int er = (lane < nb) ? d_erow[start + base + lane] : 0;
        int nb8 = (nb + 7) & ~7;
        for (int j = 0; j < nb8; j += 8) {
            float g[8];
            float m[8];
#pragma unroll
            for (int u = 0; u < 8; u++) {
                int jj = j + u;
                int r = __shfl_sync(0xffffffffu, er, jj & 31);
                bool pv = jj < nb;
                m[u] = pv ? 1.f : 0.f;
                r = pv ? r : v;
                g[u] = d_g2[(size_t)r * OUTC + lane];
            }
#pragma unroll
            for (int u = 0; u < 8; u++) acc = fmaf(m[u], g[u], acc);
        }
    }

    float pre = d_dis[v] * acc + b2[lane];
    float h = pre > 0.f ? pre : expm1f(pre);
    float p = h * Wc[lane];
#pragma unroll
    for (int off = 16; off; off >>= 1) p += __shfl_xor_sync(0xffffffffu, p, off);
    if (lane == 0) out[v] = p + bc[0];
}

// ---------------- launch ----------------
extern "C" void kernel_launch(void* const* d_in, const int* in_sizes, int n_in,
                              void* d_out, int out_size) {
    const float* x  = (const float*)d_in[0];
    const void*  ei = d_in[1];                 // [2,E], int32 or int64 (auto-detected)
    const float* W1 = (const float*)d_in[2];
    const float* b1 = (const float*)d_in[3];
    const float* W2 = (const float*)d_in[4];
    const float* b2 = (const float*)d_in[5];
    const float* Wc = (const float*)d_in[6];
    const float* bc = (const float*)d_in[7];
    float*       out = (float*)d_out;

    k_detect<<<1, 32>>>((const int*)ei);
    k_zero<<<(NN + 255) / 256, 256>>>();
    k_gemm1_hist<<<HIST_BLOCKS + GEMM_BLOCKS, 128>>>(x, W1, ei);  // hist + gemm1 overlapped
    k_bsum<<<NBLK, SCAN_B>>>();
    k_bscan<<<1, 128>>>();
    k_off<<<NBLK, SCAN_B>>>();
    k_fill<<<(EE / 4 + 255) / 256, 256>>>(ei);
    k_agg1<<<(NN + 7) / 8, 256>>>(b1, W2);
    k_agg2<<<(NN + 7) / 8, 256>>>(b2, Wc, bc, out);
}

// round 14
// speedup vs baseline: 1.1063x; 1.1063x over previous
#include <cuda_runtime.h>
#include <cstdint>

#define NN 100000
#define EE 3200000
#define IN_CH 256
#define HID 64
#define OUTC 32

#define SCAN_B 1024
#define NBLK ((NN + SCAN_B - 1) / SCAN_B)   // 98

// ---------------- scratch (no allocations allowed) ----------------
__device__ int   d_is64;                      // 1 if edge_index is int64, else 0
__device__ __align__(16) int   d_cnt[NN];     // in-degree (edges only)
__device__ __align__(16) int   d_off[NN];     // CSR start offsets
__device__ __align__(16) int   d_cur[NN];     // fill cursors
__device__ __align__(16) int   d_erow[EE];    // CSR payload: source node per edge
__device__ __align__(16) int   d_bsum[NBLK];  // per-block count sums
__device__ __align__(16) int   d_boff[NBLK];  // scanned block offsets
__device__ __align__(16) float d_dis[NN];
__device__ __align__(16) float d_g1[(size_t)NN * HID];    // dis * (x @ W1)
__device__ __align__(16) float d_g2[(size_t)NN * OUTC];   // dis * (h1 @ W2)

// ---------------- tf32 convert (round-to-nearest) ----------------
__device__ __forceinline__ float to_tf32(float f) {
    unsigned u;
    asm("cvt.rna.tf32.f32 %0, %1;" : "=r"(u) : "f"(f));
    return __uint_as_float(u);
}

// m16n8k8 tf32 MMA, explicit fragments (PTX ISA layout)
__device__ __forceinline__ void mma_tf32(float c[4], unsigned a0, unsigned a1,
                                         unsigned a2, unsigned a3,
                                         unsigned b0, unsigned b1) {
    asm volatile(
        "mma.sync.aligned.m16n8k8.row.col.f32.tf32.tf32.f32 "
        "{%0,%1,%2,%3}, {%4,%5,%6,%7}, {%8,%9}, {%0,%1,%2,%3};"
        : "+f"(c[0]), "+f"(c[1]), "+f"(c[2]), "+f"(c[3])
        : "r"(a0), "r"(a1), "r"(a2), "r"(a3), "r"(b0), "r"(b1));
}

// ---------------- dtype detector: int64 edge_index has all-zero odd words ----------------
__global__ void k_detect(const int* __restrict__ ei_w) {
    int lane = threadIdx.x;  // one warp
    int nz = 0;
#pragma unroll
    for (int j = 0; j < 8; j++) {
        long long k = (long long)(lane * 8 + j) * (EE / 512);  // < EE/2
        nz |= ei_w[2 * k + 1];
    }
    unsigned any = __ballot_sync(0xffffffffu, nz != 0);
    if (lane == 0) d_is64 = (any == 0u) ? 1 : 0;
}

// ---------------- zero histogram ----------------
__global__ void k_zero() {
    unsigned i = blockIdx.x * blockDim.x + threadIdx.x;
    if (i < (unsigned)NN) d_cnt[i] = 0;
}

// ---------------- histogram by target (col), 4 edges/thread ----------------
__global__ void k_hist(const void* __restrict__ ei) {
    unsigned e0 = (blockIdx.x * blockDim.x + threadIdx.x) * 4u;
    if (e0 >= (unsigned)EE) return;  // EE % 4 == 0
    int c[4];
    if (d_is64) {
        const long long* p = (const long long*)ei + EE;
#pragma unroll
        for (int u = 0; u < 4; u++) c[u] = (int)p[e0 + u];
    } else {
        const int* p = (const int*)ei + EE;
#pragma unroll
        for (int u = 0; u < 4; u++) c[u] = p[e0 + u];
    }
#pragma unroll
    for (int u = 0; u < 4; u++) atomicAdd(&d_cnt[c[u]], 1);
}

// ---------------- scan phase 1: per-block sums ----------------
__global__ __launch_bounds__(SCAN_B) void k_bsum() {
    __shared__ int sred[SCAN_B / 32];
    int t = threadIdx.x;
    unsigned i = blockIdx.x * SCAN_B + t;
    int c = (i < (unsigned)NN) ? d_cnt[i] : 0;
    int w = c;
#pragma unroll
    for (int off = 16; off; off >>= 1) w += __shfl_xor_sync(0xffffffffu, w, off);
    if ((t & 31) == 0) sred[t >> 5] = w;
    __syncthreads();
    if (t < 32) {
        int s = (t < SCAN_B / 32) ? sred[t] : 0;
#pragma unroll
        for (int off = 16; off; off >>= 1) s += __shfl_xor_sync(0xffffffffu, s, off);
        if (t == 0) d_bsum[blockIdx.x] = s;
    }
}

// ---------------- scan phase 2: exclusive scan of 98 block sums ----------------
__global__ void k_bscan() {
    __shared__ int sv[128];
    int t = threadIdx.x;  // 128 threads
    sv[t] = (t < NBLK) ? d_bsum[t] : 0;
    __syncthreads();
#pragma unroll
    for (int off = 1; off < 128; off <<= 1) {
        int v = (t >= off) ? sv[t - off] : 0;
        __syncthreads();
        sv[t] += v;
        __syncthreads();
    }
    if (t < NBLK) d_boff[t] = (t == 0) ? 0 : sv[t - 1];
}

// ---------------- scan phase 3: intra-block exclusive scan + finalize ----------------
__global__ __launch_bounds__(SCAN_B) void k_off() {
    __shared__ int swsum[SCAN_B / 32];
    int t = threadIdx.x;
    int lane = t & 31;
    int wp = t >> 5;
    unsigned i = blockIdx.x * SCAN_B + t;
    int c = (i < (unsigned)NN) ? d_cnt[i] : 0;
    int s = c;
#pragma unroll
    for (int off = 1; off < 32; off <<= 1) {
        int v = __shfl_up_sync(0xffffffffu, s, off);
        if (lane >= off) s += v;
    }
    if (lane == 31) swsum[wp] = s;
    __syncthreads();
    if (t < 32) {
        int ws = (t < SCAN_B / 32) ? swsum[t] : 0;
#pragma unroll
        for (int off = 1; off < 32; off <<= 1) {
            int v = __shfl_up_sync(0xffffffffu, ws, off);
            if ((t & 31) >= off) ws += v;
        }
        if (t < SCAN_B / 32) swsum[t] = ws;
    }
    __syncthreads();
    int excl = s - c + (wp ? swsum[wp - 1] : 0) + d_boff[blockIdx.x];
    if (i < (unsigned)NN) {
        d_off[i] = excl;
        d_cur[i] = excl;
        d_dis[i] = rsqrtf((float)(c + 1));  // +1 self loop
    }
}

// ---------------- fill CSR, 4 edges per thread (MLP) ----------------
__global__ void k_fill(const void* __restrict__ ei) {
    unsigned e0 = (blockIdx.x * blockDim.x + threadIdx.x) * 4u;
    if (e0 >= (unsigned)EE) return;
    int r[4], c[4];
    if (d_is64) {
        const long long* p = (const long long*)ei;
#pragma unroll
        for (int u = 0; u < 4; u++) {
            r[u] = (int)p[e0 + u];
            c[u] = (int)p[(size_t)EE + e0 + u];
        }
    } else {
        const int* p = (const int*)ei;
#pragma unroll
        for (int u = 0; u < 4; u++) {
            r[u] = p[e0 + u];
            c[u] = p[EE + e0 + u];
        }
    }
#pragma unroll
    for (int u = 0; u < 4; u++) {
        int pos = atomicAdd(&d_cur[c[u]], 1);
        d_erow[pos] = r[u];
    }
}

// ---------------- GEMM1 (manual tf32 mma.m16n8k8): g1 = dis * (x @ W1) ----------------
// 128 threads = 4 warps. Block tile M=64, N=64(=HID), K chunks of 32.
// Warp w: rows [w*16, w*16+16). 8 n-tiles of width 8.
// Fragment layout (PTX): g=lane>>2, t=lane&3.
//   A: a0=(g,t) a1=(g+8,t) a2=(g,t+4) a3=(g+8,t+4)
//   B: b0=(k=t,n) b1=(k=t+4,n)
//   C: c0=(g,2t) c1=(g,2t+1) c2=(g+8,2t) c3=(g+8,2t+1)
#define A_LD 36   // 36 % 32 == 4 -> a-frag banks 4g+t, all distinct
#define B_LD 72   // 72 % 32 == 8 -> b-frag banks 8t+g, all distinct
__global__ __launch_bounds__(128) void k_gemm1(const float* __restrict__ x,
                                               const float* __restrict__ W1) {
    __shared__ __align__(16) float sA[64 * A_LD];
    __shared__ __align__(16) float sB[32 * B_LD];
    int tid = threadIdx.x;
    int warp = tid >> 5;
    int lane = tid & 31;
    int g = lane >> 2;
    int t = lane & 3;
    int m0 = blockIdx.x * 64;

    float c[8][4];  // 8 n-tiles x 4 accum
#pragma unroll
    for (int j = 0; j < 8; j++)
#pragma unroll
        for (int q = 0; q < 4; q++) c[j][q] = 0.f;

    for (int k0 = 0; k0 < IN_CH; k0 += 32) {
        // A tile 64x32: 512 float4, 4 per thread
#pragma unroll
        for (int i = 0; i < 4; i++) {
            int idx = tid + i * 128;      // 0..511
            int r = idx >> 3;             // 8 float4 per row
            int cq = (idx & 7) * 4;
            int gm = m0 + r;
            float4 v = make_float4(0.f, 0.f, 0.f, 0.f);
            if (gm < NN) v = *(const float4*)(x + (size_t)gm * IN_CH + k0 + cq);
            float* dst = sA + r * A_LD + cq;
            dst[0] = to_tf32(v.x); dst[1] = to_tf32(v.y);
            dst[2] = to_tf32(v.z); dst[3] = to_tf32(v.w);
        }
        // B tile 32x64: 512 float4, 4 per thread
#pragma unroll
        for (int i = 0; i < 4; i++) {
            int idx = tid + i * 128;
            int r = idx >> 4;             // 16 float4 per row
            int cq = (idx & 15) * 4;
            float4 w = *(const float4*)(W1 + (size_t)(k0 + r) * HID + cq);
            float* dst = sB + r * B_LD + cq;
            dst[0] = to_tf32(w.x); dst[1] = to_tf32(w.y);
            dst[2] = to_tf32(w.z); dst[3] = to_tf32(w.w);
        }
        __syncthreads();
#pragma unroll
        for (int kk = 0; kk < 32; kk += 8) {
            int abase = (warp * 16 + g) * A_LD + kk + t;
            unsigned a0 = __float_as_uint(sA[abase]);
            unsigned a1 = __float_as_uint(sA[abase + 8 * A_LD]);
            unsigned a2 = __float_as_uint(sA[abase + 4]);
            unsigned a3 = __float_as_uint(sA[abase + 8 * A_LD + 4]);
#pragma unroll
            for (int j = 0; j < 8; j++) {
                unsigned b0 = __float_as_uint(sB[(kk + t) * B_LD + j * 8 + g]);
                unsigned b1 = __float_as_uint(sB[(kk + t + 4) * B_LD + j * 8 + g]);
                mma_tf32(c[j], a0, a1, a2, a3, b0, b1);
            }
        }
        __syncthreads();
    }

    // epilogue: write fragments directly, scaled by dis
    int row0 = m0 + warp * 16 + g;
    int row1 = row0 + 8;
    bool p0 = row0 < NN, p1 = row1 < NN;
    float s0 = p0 ? d_dis[row0] : 0.f;
    float s1 = p1 ? d_dis[row1] : 0.f;
#pragma unroll
    for (int j = 0; j < 8; j++) {
        int col = j * 8 + 2 * t;
        if (p0) *(float2*)&d_g1[(size_t)row0 * HID + col] =
            make_float2(s0 * c[j][0], s0 * c[j][1]);
        if (p1) *(float2*)&d_g1[(size_t)row1 * HID + col] =
            make_float2(s1 * c[j][2], s1 * c[j][3]);
    }
}

// ---------------- agg1 fused: gather g1 + self + ELU + GEMM2 -> g2 ----------------
// 1 warp per node; lane owns features 2*lane, 2*lane+1. W2 in shared.
__global__ __launch_bounds__(256) void k_agg1(const float* __restrict__ b1,
                                              const float* __restrict__ W2) {
    __shared__ float sW[64][32];   // W2
    __shared__ float sh[8][64];    // h per warp
    int t = threadIdx.x;
    int warp = t >> 5;
    int lane = t & 31;
    ((float4*)sW)[t] = ((const float4*)W2)[t];
    ((float4*)sW)[t + 256] = ((const float4*)W2)[t + 256];
    __syncthreads();

    int v = blockIdx.x * 8 + warp;
    if (v >= NN) return;

    int start = d_off[v];
    int cnt = d_cnt[v];
    float2 acc = *(const float2*)(d_g1 + (size_t)v * HID + lane * 2);  // self

    for (int base = 0; base < cnt; base += 32) {
        int nb = cnt - base; if (nb > 32) nb = 32;
        int er = (lane < nb) ? d_erow[start + base + lane] : 0;
        int nb8 = (nb + 7) & ~7;
        for (int j = 0; j < nb8; j += 8) {
            float2 g[8];
            bool pv[8];
#pragma unroll
            for (int u = 0; u < 8; u++) {
                int jj = j + u;
                int r = __shfl_sync(0xffffffffu, er, jj & 31);
                pv[u] = jj < nb;
                r = pv[u] ? r : v;  // harmless in-range dummy
                g[u] = *(const float2*)(d_g1 + (size_t)r * HID + lane * 2);
            }
#pragma unroll
            for (int u = 0; u < 8; u++)
                if (pv[u]) { acc.x += g[u].x; acc.y += g[u].y; }
        }
    }

    float s = d_dis[v];
    float p0 = s * acc.x + b1[lane * 2];
    float p1 = s * acc.y + b1[lane * 2 + 1];
    float h0 = p0 > 0.f ? p0 : expm1f(p0);
    float h1 = p1 > 0.f ? p1 : expm1f(p1);
    sh[warp][lane * 2] = h0;
    sh[warp][lane * 2 + 1] = h1;
    __syncwarp();

    // GEMM2 for this node: out[o=lane] = sum_f h[f] * W2[f][o]
    float o_acc = 0.f;
#pragma unroll
    for (int f = 0; f < 64; f++) o_acc = fmaf(sh[warp][f], sW[f][lane], o_acc);
    d_g2[(size_t)v * OUTC + lane] = s * o_acc;
}

// ---------------- agg2 fused: gather g2 + self + ELU + dot(Wc) -> out ----------------
__global__ __launch_bounds__(256) void k_agg2(const float* __restrict__ b2,
                                              const float* __restrict__ Wc,
                                              const float* __restrict__ bc,
                                              float* __restrict__ out) {
    int t = threadIdx.x;
    int warp = t >> 5;
    int lane = t & 31;
    int v = blockIdx.x * 8 + warp;
    if (v >= NN) return;

    int start = d_off[v];
    int cnt = d_cnt[v];
    float acc = d_g2[(size_t)v * OUTC + lane];  // self

    for (int base = 0; base < cnt; base += 32) {
        int nb = cnt - base; if (nb > 32) nb = 32;
        int er = (lane < nb) ? d_erow[start + base + lane] : 0;
        int nb8 = (nb + 7) & ~7;
        for (int j = 0; j < nb8; j += 8) {
            float g[8];
            bool pv[8];
#pragma unroll
            for (int u = 0; u < 8; u++) {
                int jj = j + u;
                int r = __shfl_sync(0xffffffffu, er, jj & 31);
                pv[u] = jj < nb;
                r = pv[u] ? r : v;
                g[u] = d_g2[(size_t)r * OUTC + lane];
            }
#pragma unroll
            for (int u = 0; u < 8; u++)
                if (pv[u]) acc += g[u];
        }
    }

    float pre = d_dis[v] * acc + b2[lane];
    float h = pre > 0.f ? pre : expm1f(pre);
    float p = h * Wc[lane];
#pragma unroll
    for (int off = 16; off; off >>= 1) p += __shfl_xor_sync(0xffffffffu, p, off);
    if (lane == 0) out[v] = p + bc[0];
}

// ---------------- launch ----------------
extern "C" void kernel_launch(void* const* d_in, const int* in_sizes, int n_in,
                              void* d_out, int out_size) {
    const float* x  = (const float*)d_in[0];
    const void*  ei = d_in[1];                 // [2,E], int32 or int64 (auto-detected)
    const float* W1 = (const float*)d_in[2];
    const float* b1 = (const float*)d_in[3];
    const float* W2 = (const float*)d_in[4];
    const float* b2 = (const float*)d_in[5];
    const float* Wc = (const float*)d_in[6];
    const float* bc = (const float*)d_in[7];
    float*       out = (float*)d_out;

    k_detect<<<1, 32>>>((const int*)ei);
    k_zero<<<(NN + 255) / 256, 256>>>();
    k_hist<<<(EE / 4 + 255) / 256, 256>>>(ei);
    k_bsum<<<NBLK, SCAN_B>>>();
    k_bscan<<<1, 128>>>();
    k_off<<<NBLK, SCAN_B>>>();
    k_fill<<<(EE / 4 + 255) / 256, 256>>>(ei);
    k_gemm1<<<(NN + 63) / 64, 128>>>(x, W1);
    k_agg1<<<(NN + 7) / 8, 256>>>(b1, W2);
    k_agg2<<<(NN + 7) / 8, 256>>>(b2, Wc, bc, out);
}

// round 15
// speedup vs baseline: 1.1707x; 1.0582x over previous
#include <cuda_runtime.h>
#include <cstdint>

#define NN 100000
#define EE 3200000
#define IN_CH 256
#define HID 64
#define OUTC 32

#define SCAN_B 1024
#define NBLK ((NN + SCAN_B - 1) / SCAN_B)   // 98

// ---------------- scratch (no allocations allowed) ----------------
__device__ int   d_is64;                      // 1 if edge_index is int64, else 0
__device__ __align__(16) int   d_cnt[NN];     // in-degree (edges only)
__device__ __align__(16) int   d_off[NN];     // CSR start offsets
__device__ __align__(16) int   d_cur[NN];     // fill cursors
__device__ __align__(16) int   d_erow[EE];    // CSR payload: source node per edge
__device__ __align__(16) int   d_bsum[NBLK];  // per-block count sums
__device__ __align__(16) int   d_boff[NBLK];  // scanned block offsets
__device__ __align__(16) float d_dis[NN];
__device__ __align__(16) float d_g1[(size_t)NN * HID];    // dis * (x @ W1)
__device__ __align__(16) float d_g2[(size_t)NN * OUTC];   // dis * (h1 @ W2)

// ---------------- tf32 convert (round-to-nearest) ----------------
__device__ __forceinline__ float to_tf32(float f) {
    unsigned u;
    asm("cvt.rna.tf32.f32 %0, %1;" : "=r"(u) : "f"(f));
    return __uint_as_float(u);
}

// m16n8k8 tf32 MMA, explicit fragments (PTX ISA layout)
__device__ __forceinline__ void mma_tf32(float c[4], unsigned a0, unsigned a1,
                                         unsigned a2, unsigned a3,
                                         unsigned b0, unsigned b1) {
    asm volatile(
        "mma.sync.aligned.m16n8k8.row.col.f32.tf32.tf32.f32 "
        "{%0,%1,%2,%3}, {%4,%5,%6,%7}, {%8,%9}, {%0,%1,%2,%3};"
        : "+f"(c[0]), "+f"(c[1]), "+f"(c[2]), "+f"(c[3])
        : "r"(a0), "r"(a1), "r"(a2), "r"(a3), "r"(b0), "r"(b1));
}

// ---------------- dtype detector: int64 edge_index has all-zero odd words ----------------
__global__ void k_detect(const int* __restrict__ ei_w) {
    int lane = threadIdx.x;  // one warp
    int nz = 0;
#pragma unroll
    for (int j = 0; j < 8; j++) {
        long long k = (long long)(lane * 8 + j) * (EE / 512);  // < EE/2
        nz |= ei_w[2 * k + 1];
    }
    unsigned any = __ballot_sync(0xffffffffu, nz != 0);
    if (lane == 0) d_is64 = (any == 0u) ? 1 : 0;
}

// ---------------- zero histogram ----------------
__global__ void k_zero() {
    unsigned i = blockIdx.x * blockDim.x + threadIdx.x;
    if (i < (unsigned)NN) d_cnt[i] = 0;
}

// ---------------- histogram by target (col), 4 edges/thread ----------------
__global__ void k_hist(const void* __restrict__ ei) {
    unsigned e0 = (blockIdx.x * blockDim.x + threadIdx.x) * 4u;
    if (e0 >= (unsigned)EE) return;  // EE % 4 == 0
    int c[4];
    if (d_is64) {
        const long long* p = (const long long*)ei + EE;
#pragma unroll
        for (int u = 0; u < 4; u++) c[u] = (int)p[e0 + u];
    } else {
        const int* p = (const int*)ei + EE;
#pragma unroll
        for (int u = 0; u < 4; u++) c[u] = p[e0 + u];
    }
#pragma unroll
    for (int u = 0; u < 4; u++) atomicAdd(&d_cnt[c[u]], 1);
}

// ---------------- scan phase 1: per-block sums ----------------
__global__ __launch_bounds__(SCAN_B) void k_bsum() {
    __shared__ int sred[SCAN_B / 32];
    int t = threadIdx.x;
    unsigned i = blockIdx.x * SCAN_B + t;
    int c = (i < (unsigned)NN) ? d_cnt[i] : 0;
    int w = c;
#pragma unroll
    for (int off = 16; off; off >>= 1) w += __shfl_xor_sync(0xffffffffu, w, off);
    if ((t & 31) == 0) sred[t >> 5] = w;
    __syncthreads();
    if (t < 32) {
        int s = (t < SCAN_B / 32) ? sred[t] : 0;
#pragma unroll
        for (int off = 16; off; off >>= 1) s += __shfl_xor_sync(0xffffffffu, s, off);
        if (t == 0) d_bsum[blockIdx.x] = s;
    }
}

// ---------------- scan phase 2: exclusive scan of 98 block sums ----------------
__global__ void k_bscan() {
    __shared__ int sv[128];
    int t = threadIdx.x;  // 128 threads
    sv[t] = (t < NBLK) ? d_bsum[t] : 0;
    __syncthreads();
#pragma unroll
    for (int off = 1; off < 128; off <<= 1) {
        int v = (t >= off) ? sv[t - off] : 0;
        __syncthreads();
        sv[t] += v;
        __syncthreads();
    }
    if (t < NBLK) d_boff[t] = (t == 0) ? 0 : sv[t - 1];
}

// ---------------- scan phase 3: intra-block exclusive scan + finalize ----------------
__global__ __launch_bounds__(SCAN_B) void k_off() {
    __shared__ int swsum[SCAN_B / 32];
    int t = threadIdx.x;
    int lane = t & 31;
    int wp = t >> 5;
    unsigned i = blockIdx.x * SCAN_B + t;
    int c = (i < (unsigned)NN) ? d_cnt[i] : 0;
    int s = c;
#pragma unroll
    for (int off = 1; off < 32; off <<= 1) {
        int v = __shfl_up_sync(0xffffffffu, s, off);
        if (lane >= off) s += v;
    }
    if (lane == 31) swsum[wp] = s;
    __syncthreads();
    if (t < 32) {
        int ws = (t < SCAN_B / 32) ? swsum[t] : 0;
#pragma unroll
        for (int off = 1; off < 32; off <<= 1) {
            int v = __shfl_up_sync(0xffffffffu, ws, off);
            if ((t & 31) >= off) ws += v;
        }
        if (t < SCAN_B / 32) swsum[t] = ws;
    }
    __syncthreads();
    int excl = s - c + (wp ? swsum[wp - 1] : 0) + d_boff[blockIdx.x];
    if (i < (unsigned)NN) {
        d_off[i] = excl;
        d_cur[i] = excl;
        d_dis[i] = rsqrtf((float)(c + 1));  // +1 self loop
    }
}

// ---------------- fill CSR, 4 edges per thread (MLP) ----------------
__global__ void k_fill(const void* __restrict__ ei) {
    unsigned e0 = (blockIdx.x * blockDim.x + threadIdx.x) * 4u;
    if (e0 >= (unsigned)EE) return;
    int r[4], c[4];
    if (d_is64) {
        const long long* p = (const long long*)ei;
#pragma unroll
        for (int u = 0; u < 4; u++) {
            r[u] = (int)p[e0 + u];
            c[u] = (int)p[(size_t)EE + e0 + u];
        }
    } else {
        const int* p = (const int*)ei;
#pragma unroll
        for (int u = 0; u < 4; u++) {
            r[u] = p[e0 + u];
            c[u] = p[EE + e0 + u];
        }
    }
#pragma unroll
    for (int u = 0; u < 4; u++) {
        int pos = atomicAdd(&d_cur[c[u]], 1);
        d_erow[pos] = r[u];
    }
}

// ---------------- GEMM1 (manual tf32 mma.m16n8k8): g1 = dis * (x @ W1) ----------------
#define A_LD 36   // 36 % 32 == 4 -> a-frag banks 4g+t, all distinct
#define B_LD 72   // 72 % 32 == 8 -> b-frag banks 8t+g, all distinct
__global__ __launch_bounds__(128) void k_gemm1(const float* __restrict__ x,
                                               const float* __restrict__ W1) {
    __shared__ __align__(16) float sA[64 * A_LD];
    __shared__ __align__(16) float sB[32 * B_LD];
    int tid = threadIdx.x;
    int warp = tid >> 5;
    int lane = tid & 31;
    int g = lane >> 2;
    int t = lane & 3;
    int m0 = blockIdx.x * 64;

    float c[8][4];
#pragma unroll
    for (int j = 0; j < 8; j++)
#pragma unroll
        for (int q = 0; q < 4; q++) c[j][q] = 0.f;

    for (int k0 = 0; k0 < IN_CH; k0 += 32) {
#pragma unroll
        for (int i = 0; i < 4; i++) {
            int idx = tid + i * 128;
            int r = idx >> 3;
            int cq = (idx & 7) * 4;
            int gm = m0 + r;
            float4 v = make_float4(0.f, 0.f, 0.f, 0.f);
            if (gm < NN) v = *(const float4*)(x + (size_t)gm * IN_CH + k0 + cq);
            float* dst = sA + r * A_LD + cq;
            dst[0] = to_tf32(v.x); dst[1] = to_tf32(v.y);
            dst[2] = to_tf32(v.z); dst[3] = to_tf32(v.w);
        }
#pragma unroll
        for (int i = 0; i < 4; i++) {
            int idx = tid + i * 128;
            int r = idx >> 4;
            int cq = (idx & 15) * 4;
            float4 w = *(const float4*)(W1 + (size_t)(k0 + r) * HID + cq);
            float* dst = sB + r * B_LD + cq;
            dst[0] = to_tf32(w.x); dst[1] = to_tf32(w.y);
            dst[2] = to_tf32(w.z); dst[3] = to_tf32(w.w);
        }
        __syncthreads();
#pragma unroll
        for (int kk = 0; kk < 32; kk += 8) {
            int abase = (warp * 16 + g) * A_LD + kk + t;
            unsigned a0 = __float_as_uint(sA[abase]);
            unsigned a1 = __float_as_uint(sA[abase + 8 * A_LD]);
            unsigned a2 = __float_as_uint(sA[abase + 4]);
            unsigned a3 = __float_as_uint(sA[abase + 8 * A_LD + 4]);
#pragma unroll
            for (int j = 0; j < 8; j++) {
                unsigned b0 = __float_as_uint(sB[(kk + t) * B_LD + j * 8 + g]);
                unsigned b1 = __float_as_uint(sB[(kk + t + 4) * B_LD + j * 8 + g]);
                mma_tf32(c[j], a0, a1, a2, a3, b0, b1);
            }
        }
        __syncthreads();
    }

    int row0 = m0 + warp * 16 + g;
    int row1 = row0 + 8;
    bool p0 = row0 < NN, p1 = row1 < NN;
    float s0 = p0 ? d_dis[row0] : 0.f;
    float s1 = p1 ? d_dis[row1] : 0.f;
#pragma unroll
    for (int j = 0; j < 8; j++) {
        int col = j * 8 + 2 * t;
        if (p0) *(float2*)&d_g1[(size_t)row0 * HID + col] =
            make_float2(s0 * c[j][0], s0 * c[j][1]);
        if (p1) *(float2*)&d_g1[(size_t)row1 * HID + col] =
            make_float2(s1 * c[j][2], s1 * c[j][3]);
    }
}

// ---------------- agg1: 2 edges/warp, float4/lane gather + ELU + GEMM2 -> g2 ----------------
// Half-warps process alternate edges; lane li=lane&15 owns features [li*4, li*4+4).
__global__ __launch_bounds__(256) void k_agg1(const float* __restrict__ b1,
                                              const float* __restrict__ W2) {
    __shared__ float sW[64][32];   // W2
    __shared__ float sh[8][64];    // h per warp
    int t = threadIdx.x;
    int warp = t >> 5;
    int lane = t & 31;
    ((float4*)sW)[t] = ((const float4*)W2)[t];
    ((float4*)sW)[t + 256] = ((const float4*)W2)[t + 256];
    __syncthreads();

    int v = blockIdx.x * 8 + warp;
    if (v >= NN) return;

    int start = d_off[v];
    int cnt = d_cnt[v];
    int half = lane >> 4;   // 0/1: which edge of the pair
    int li = lane & 15;     // feature quad

    float4 acc = make_float4(0.f, 0.f, 0.f, 0.f);
    if (half == 0)  // self term on half 0 only
        acc = *(const float4*)(d_g1 + (size_t)v * HID + li * 4);

    for (int base = 0; base < cnt; base += 32) {
        int nb = cnt - base; if (nb > 32) nb = 32;
        int er = (lane < nb) ? d_erow[start + base + lane] : 0;
        for (int j = 0; j < nb; j += 16) {
            float4 g[8];
            bool pv[8];
#pragma unroll
            for (int u = 0; u < 8; u++) {
                int jj = j + 2 * u + half;
                int r = __shfl_sync(0xffffffffu, er, jj & 31);
                pv[u] = jj < nb;
                r = pv[u] ? r : v;  // in-range dummy
                g[u] = *(const float4*)(d_g1 + (size_t)r * HID + li * 4);
            }
#pragma unroll
            for (int u = 0; u < 8; u++)
                if (pv[u]) {
                    acc.x += g[u].x; acc.y += g[u].y;
                    acc.z += g[u].z; acc.w += g[u].w;
                }
        }
    }

    // combine halves
    acc.x += __shfl_xor_sync(0xffffffffu, acc.x, 16);
    acc.y += __shfl_xor_sync(0xffffffffu, acc.y, 16);
    acc.z += __shfl_xor_sync(0xffffffffu, acc.z, 16);
    acc.w += __shfl_xor_sync(0xffffffffu, acc.w, 16);

    float s = d_dis[v];
    if (half == 0) {
        float4 bb = *(const float4*)(b1 + li * 4);
        float p0 = s * acc.x + bb.x;
        float p1 = s * acc.y + bb.y;
        float p2 = s * acc.z + bb.z;
        float p3 = s * acc.w + bb.w;
        float4 h;
        h.x = p0 > 0.f ? p0 : expm1f(p0);
        h.y = p1 > 0.f ? p1 : expm1f(p1);
        h.z = p2 > 0.f ? p2 : expm1f(p2);
        h.w = p3 > 0.f ? p3 : expm1f(p3);
        *(float4*)&sh[warp][li * 4] = h;
    }
    __syncwarp();

    // GEMM2 for this node: out[o=lane] = sum_f h[f] * W2[f][o]
    float o_acc = 0.f;
#pragma unroll
    for (int f = 0; f < 64; f++) o_acc = fmaf(sh[warp][f], sW[f][lane], o_acc);
    d_g2[(size_t)v * OUTC + lane] = s * o_acc;
}

// ---------------- agg2: 2 edges/warp, float2/lane gather + ELU + dot(Wc) -> out ----------------
__global__ __launch_bounds__(256) void k_agg2(const float* __restrict__ b2,
                                              const float* __restrict__ Wc,
                                              const float* __restrict__ bc,
                                              float* __restrict__ out) {
    int t = threadIdx.x;
    int warp = t >> 5;
    int lane = t & 31;
    int v = blockIdx.x * 8 + warp;
    if (v >= NN) return;

    int start = d_off[v];
    int cnt = d_cnt[v];
    int half = lane >> 4;
    int li = lane & 15;     // feature pair

    float2 acc = make_float2(0.f, 0.f);
    if (half == 0)
        acc = *(const float2*)(d_g2 + (size_t)v * OUTC + li * 2);  // self

    for (int base = 0; base < cnt; base += 32) {
        int nb = cnt - base; if (nb > 32) nb = 32;
        int er = (lane < nb) ? d_erow[start + base + lane] : 0;
        for (int j = 0; j < nb; j += 16) {
            float2 g[8];
            bool pv[8];
#pragma unroll
            for (int u = 0; u < 8; u++) {
                int jj = j + 2 * u + half;
                int r = __shfl_sync(0xffffffffu, er, jj & 31);
                pv[u] = jj < nb;
                r = pv[u] ? r : v;
                g[u] = *(const float2*)(d_g2 + (size_t)r * OUTC + li * 2);
            }
#pragma unroll
            for (int u = 0; u < 8; u++)
                if (pv[u]) { acc.x += g[u].x; acc.y += g[u].y; }
        }
    }

    acc.x += __shfl_xor_sync(0xffffffffu, acc.x, 16);
    acc.y += __shfl_xor_sync(0xffffffffu, acc.y, 16);

    float p = 0.f;
    if (half == 0) {
        float s = d_dis[v];
        float pre0 = s * acc.x + b2[li * 2];
        float pre1 = s * acc.y + b2[li * 2 + 1];
        float h0 = pre0 > 0.f ? pre0 : expm1f(pre0);
        float h1 = pre1 > 0.f ? pre1 : expm1f(pre1);
        p = h0 * Wc[li * 2] + h1 * Wc[li * 2 + 1];
    }
#pragma unroll
    for (int off = 16; off; off >>= 1) p += __shfl_xor_sync(0xffffffffu, p, off);
    if (lane == 0) out[v] = p + bc[0];
}

// ---------------- launch ----------------
extern "C" void kernel_launch(void* const* d_in, const int* in_sizes, int n_in,
                              void* d_out, int out_size) {
    const float* x  = (const float*)d_in[0];
    const void*  ei = d_in[1];                 // [2,E], int32 or int64 (auto-detected)
    const float* W1 = (const float*)d_in[2];
    const float* b1 = (const float*)d_in[3];
    const float* W2 = (const float*)d_in[4];
    const float* b2 = (const float*)d_in[5];
    const float* Wc = (const float*)d_in[6];
    const float* bc = (const float*)d_in[7];
    float*       out = (float*)d_out;

    k_detect<<<1, 32>>>((const int*)ei);
    k_zero<<<(NN + 255) / 256, 256>>>();
    k_hist<<<(EE / 4 + 255) / 256, 256>>>(ei);
    k_bsum<<<NBLK, SCAN_B>>>();
    k_bscan<<<1, 128>>>();
    k_off<<<NBLK, SCAN_B>>>();
    k_fill<<<(EE / 4 + 255) / 256, 256>>>(ei);
    k_gemm1<<<(NN + 63) / 64, 128>>>(x, W1);
    k_agg1<<<(NN + 7) / 8, 256>>>(b1, W2);
    k_agg2<<<(NN + 7) / 8, 256>>>(b2, Wc, bc, out);
}

// round 16
// speedup vs baseline: 1.1954x; 1.0211x over previous
#include <cuda_runtime.h>
#include <cuda_fp16.h>
#include <cstdint>

#define NN 100000
#define EE 3200000
#define IN_CH 256
#define HID 64
#define OUTC 32

#define SCAN_B 1024
#define NBLK ((NN + SCAN_B - 1) / SCAN_B)   // 98

// ---------------- scratch (no allocations allowed) ----------------
__device__ int   d_is64;                      // 1 if edge_index is int64, else 0
__device__ __align__(16) int   d_cnt[NN];     // in-degree (edges only)
__device__ __align__(16) int   d_off[NN];     // CSR start offsets
__device__ __align__(16) int   d_cur[NN];     // fill cursors
__device__ __align__(16) int   d_erow[EE];    // CSR payload: source node per edge
__device__ __align__(16) int   d_bsum[NBLK];  // per-block count sums
__device__ __align__(16) int   d_boff[NBLK];  // scanned block offsets
__device__ __align__(16) float d_dis[NN];
__device__ __align__(16) float d_g1[(size_t)NN * HID];      // fp32 dis*(x@W1) (self terms)
__device__ __align__(16) unsigned d_g1h[(size_t)NN * 32];   // half2-packed shadow (gathers)
__device__ __align__(16) float d_g2[(size_t)NN * OUTC];     // fp32 dis*(h1@W2) (self terms)
__device__ __align__(16) unsigned d_g2h[(size_t)NN * 16];   // half2-packed shadow (gathers)

// ---------------- tf32 convert (round-to-nearest) ----------------
__device__ __forceinline__ float to_tf32(float f) {
    unsigned u;
    asm("cvt.rna.tf32.f32 %0, %1;" : "=r"(u) : "f"(f));
    return __uint_as_float(u);
}

// m16n8k8 tf32 MMA, explicit fragments (PTX ISA layout)
__device__ __forceinline__ void mma_tf32(float c[4], unsigned a0, unsigned a1,
                                         unsigned a2, unsigned a3,
                                         unsigned b0, unsigned b1) {
    asm volatile(
        "mma.sync.aligned.m16n8k8.row.col.f32.tf32.tf32.f32 "
        "{%0,%1,%2,%3}, {%4,%5,%6,%7}, {%8,%9}, {%0,%1,%2,%3};"
        : "+f"(c[0]), "+f"(c[1]), "+f"(c[2]), "+f"(c[3])
        : "r"(a0), "r"(a1), "r"(a2), "r"(a3), "r"(b0), "r"(b1));
}

// ---------------- zero histogram + dtype detect (block 0) ----------------
__global__ void k_zero(const int* __restrict__ ei_w) {
    unsigned i = blockIdx.x * blockDim.x + threadIdx.x;
    if (i < (unsigned)NN) d_cnt[i] = 0;
    if (blockIdx.x == 0 && threadIdx.x < 32) {
        int lane = threadIdx.x;
        int nz = 0;
#pragma unroll
        for (int j = 0; j < 8; j++) {
            long long k = (long long)(lane * 8 + j) * (EE / 512);  // < EE/2
            nz |= ei_w[2 * k + 1];
        }
        unsigned any = __ballot_sync(0xffffffffu, nz != 0);
        if (lane == 0) d_is64 = (any == 0u) ? 1 : 0;
    }
}

// ---------------- histogram by target (col), 4 edges/thread ----------------
__global__ void k_hist(const void* __restrict__ ei) {
    unsigned e0 = (blockIdx.x * blockDim.x + threadIdx.x) * 4u;
    if (e0 >= (unsigned)EE) return;  // EE % 4 == 0
    int c[4];
    if (d_is64) {
        const long long* p = (const long long*)ei + EE;
#pragma unroll
        for (int u = 0; u < 4; u++) c[u] = (int)p[e0 + u];
    } else {
        const int* p = (const int*)ei + EE;
#pragma unroll
        for (int u = 0; u < 4; u++) c[u] = p[e0 + u];
    }
#pragma unroll
    for (int u = 0; u < 4; u++) atomicAdd(&d_cnt[c[u]], 1);
}

// ---------------- scan phase 1: per-block sums ----------------
__global__ __launch_bounds__(SCAN_B) void k_bsum() {
    __shared__ int sred[SCAN_B / 32];
    int t = threadIdx.x;
    unsigned i = blockIdx.x * SCAN_B + t;
    int c = (i < (unsigned)NN) ? d_cnt[i] : 0;
    int w = c;
#pragma unroll
    for (int off = 16; off; off >>= 1) w += __shfl_xor_sync(0xffffffffu, w, off);
    if ((t & 31) == 0) sred[t >> 5] = w;
    __syncthreads();
    if (t < 32) {
        int s = (t < SCAN_B / 32) ? sred[t] : 0;
#pragma unroll
        for (int off = 16; off; off >>= 1) s += __shfl_xor_sync(0xffffffffu, s, off);
        if (t == 0) d_bsum[blockIdx.x] = s;
    }
}

// ---------------- scan phase 2: exclusive scan of 98 block sums ----------------
__global__ void k_bscan() {
    __shared__ int sv[128];
    int t = threadIdx.x;  // 128 threads
    sv[t] = (t < NBLK) ? d_bsum[t] : 0;
    __syncthreads();
#pragma unroll
    for (int off = 1; off < 128; off <<= 1) {
        int v = (t >= off) ? sv[t - off] : 0;
        __syncthreads();
        sv[t] += v;
        __syncthreads();
    }
    if (t < NBLK) d_boff[t] = (t == 0) ? 0 : sv[t - 1];
}

// ---------------- scan phase 3: intra-block exclusive scan + finalize ----------------
__global__ __launch_bounds__(SCAN_B) void k_off() {
    __shared__ int swsum[SCAN_B / 32];
    int t = threadIdx.x;
    int lane = t & 31;
    int wp = t >> 5;
    unsigned i = blockIdx.x * SCAN_B + t;
    int c = (i < (unsigned)NN) ? d_cnt[i] : 0;
    int s = c;
#pragma unroll
    for (int off = 1; off < 32; off <<= 1) {
        int v = __shfl_up_sync(0xffffffffu, s, off);
        if (lane >= off) s += v;
    }
    if (lane == 31) swsum[wp] = s;
    __syncthreads();
    if (t < 32) {
        int ws = (t < SCAN_B / 32) ? swsum[t] : 0;
#pragma unroll
        for (int off = 1; off < 32; off <<= 1) {
            int v = __shfl_up_sync(0xffffffffu, ws, off);
            if ((t & 31) >= off) ws += v;
        }
        if (t < SCAN_B / 32) swsum[t] = ws;
    }
    __syncthreads();
    int excl = s - c + (wp ? swsum[wp - 1] : 0) + d_boff[blockIdx.x];
    if (i < (unsigned)NN) {
        d_off[i] = excl;
        d_cur[i] = excl;
        d_dis[i] = rsqrtf((float)(c + 1));  // +1 self loop
    }
}

// ---------------- fill CSR, 4 edges per thread (MLP) ----------------
__global__ void k_fill(const void* __restrict__ ei) {
    unsigned e0 = (blockIdx.x * blockDim.x + threadIdx.x) * 4u;
    if (e0 >= (unsigned)EE) return;
    int r[4], c[4];
    if (d_is64) {
        const long long* p = (const long long*)ei;
#pragma unroll
        for (int u = 0; u < 4; u++) {
            r[u] = (int)p[e0 + u];
            c[u] = (int)p[(size_t)EE + e0 + u];
        }
    } else {
        const int* p = (const int*)ei;
#pragma unroll
        for (int u = 0; u < 4; u++) {
            r[u] = p[e0 + u];
            c[u] = p[EE + e0 + u];
        }
    }
#pragma unroll
    for (int u = 0; u < 4; u++) {
        int pos = atomicAdd(&d_cur[c[u]], 1);
        d_erow[pos] = r[u];
    }
}

// ---------------- GEMM1 (manual tf32 mma.m16n8k8): g1 = dis * (x @ W1) ----------------
#define A_LD 36   // 36 % 32 == 4 -> a-frag banks 4g+t, all distinct
#define B_LD 72   // 72 % 32 == 8 -> b-frag banks 8t+g, all distinct
__global__ __launch_bounds__(128) void k_gemm1(const float* __restrict__ x,
                                               const float* __restrict__ W1) {
    __shared__ __align__(16) float sA[64 * A_LD];
    __shared__ __align__(16) float sB[32 * B_LD];
    int tid = threadIdx.x;
    int warp = tid >> 5;
    int lane = tid & 31;
    int g = lane >> 2;
    int t = lane & 3;
    int m0 = blockIdx.x * 64;

    float c[8][4];
#pragma unroll
    for (int j = 0; j < 8; j++)
#pragma unroll
        for (int q = 0; q < 4; q++) c[j][q] = 0.f;

    for (int k0 = 0; k0 < IN_CH; k0 += 32) {
#pragma unroll
        for (int i = 0; i < 4; i++) {
            int idx = tid + i * 128;
            int r = idx >> 3;
            int cq = (idx & 7) * 4;
            int gm = m0 + r;
            float4 v = make_float4(0.f, 0.f, 0.f, 0.f);
            if (gm < NN) v = *(const float4*)(x + (size_t)gm * IN_CH + k0 + cq);
            float* dst = sA + r * A_LD + cq;
            dst[0] = to_tf32(v.x); dst[1] = to_tf32(v.y);
            dst[2] = to_tf32(v.z); dst[3] = to_tf32(v.w);
        }
#pragma unroll
        for (int i = 0; i < 4; i++) {
            int idx = tid + i * 128;
            int r = idx >> 4;
            int cq = (idx & 15) * 4;
            float4 w = *(const float4*)(W1 + (size_t)(k0 + r) * HID + cq);
            float* dst = sB + r * B_LD + cq;
            dst[0] = to_tf32(w.x); dst[1] = to_tf32(w.y);
            dst[2] = to_tf32(w.z); dst[3] = to_tf32(w.w);
        }
        __syncthreads();
#pragma unroll
        for (int kk = 0; kk < 32; kk += 8) {
            int abase = (warp * 16 + g) * A_LD + kk + t;
            unsigned a0 = __float_as_uint(sA[abase]);
            unsigned a1 = __float_as_uint(sA[abase + 8 * A_LD]);
            unsigned a2 = __float_as_uint(sA[abase + 4]);
            unsigned a3 = __float_as_uint(sA[abase + 8 * A_LD + 4]);
#pragma unroll
            for (int j = 0; j < 8; j++) {
                unsigned b0 = __float_as_uint(sB[(kk + t) * B_LD + j * 8 + g]);
                unsigned b1 = __float_as_uint(sB[(kk + t + 4) * B_LD + j * 8 + g]);
                mma_tf32(c[j], a0, a1, a2, a3, b0, b1);
            }
        }
        __syncthreads();
    }

    int row0 = m0 + warp * 16 + g;
    int row1 = row0 + 8;
    bool p0 = row0 < NN, p1 = row1 < NN;
    float s0 = p0 ? d_dis[row0] : 0.f;
    float s1 = p1 ? d_dis[row1] : 0.f;
#pragma unroll
    for (int j = 0; j < 8; j++) {
        int col = j * 8 + 2 * t;
        if (p0) {
            float a = s0 * c[j][0], b = s0 * c[j][1];
            *(float2*)&d_g1[(size_t)row0 * HID + col] = make_float2(a, b);
            __half2 h = __floats2half2_rn(a, b);
            d_g1h[(size_t)row0 * 32 + (col >> 1)] = *(unsigned*)&h;
        }
        if (p1) {
            float a = s1 * c[j][2], b = s1 * c[j][3];
            *(float2*)&d_g1[(size_t)row1 * HID + col] = make_float2(a, b);
            __half2 h = __floats2half2_rn(a, b);
            d_g1h[(size_t)row1 * 32 + (col >> 1)] = *(unsigned*)&h;
        }
    }
}

// ---------------- agg1: 2 edges/warp, fp16 uint2/lane gather + ELU + GEMM2 -> g2 ----------------
// Half-warps process alternate edges; lane li=lane&15 owns features [li*4, li*4+4).
__global__ __launch_bounds__(256) void k_agg1(const float* __restrict__ b1,
                                              const float* __restrict__ W2) {
    __shared__ float sW[64][32];   // W2
    __shared__ float sh[8][64];    // h per warp
    int t = threadIdx.x;
    int warp = t >> 5;
    int lane = t & 31;
    ((float4*)sW)[t] = ((const float4*)W2)[t];
    ((float4*)sW)[t + 256] = ((const float4*)W2)[t + 256];
    __syncthreads();

    int v = blockIdx.x * 8 + warp;
    if (v >= NN) return;

    int start = d_off[v];
    int cnt = d_cnt[v];
    int half = lane >> 4;   // 0/1: which edge of the pair
    int li = lane & 15;     // feature quad

    float4 acc = make_float4(0.f, 0.f, 0.f, 0.f);
    if (half == 0)  // self term on half 0 only (fp32)
        acc = *(const float4*)(d_g1 + (size_t)v * HID + li * 4);

    for (int base = 0; base < cnt; base += 32) {
        int nb = cnt - base; if (nb > 32) nb = 32;
        int er = (lane < nb) ? d_erow[start + base + lane] : 0;
        for (int j = 0; j < nb; j += 16) {
            uint2 g[8];
            bool pv[8];
#pragma unroll
            for (int u = 0; u < 8; u++) {
                int jj = j + 2 * u + half;
                int r = __shfl_sync(0xffffffffu, er, jj & 31);
                pv[u] = jj < nb;
                r = pv[u] ? r : v;  // in-range dummy
                g[u] = *(const uint2*)&d_g1h[(size_t)r * 32 + li * 2];
            }
#pragma unroll
            for (int u = 0; u < 8; u++)
                if (pv[u]) {
                    float2 f0 = __half22float2(*(__half2*)&g[u].x);
                    float2 f1 = __half22float2(*(__half2*)&g[u].y);
                    acc.x += f0.x; acc.y += f0.y;
                    acc.z += f1.x; acc.w += f1.y;
                }
        }
    }

    // combine halves
    acc.x += __shfl_xor_sync(0xffffffffu, acc.x, 16);
    acc.y += __shfl_xor_sync(0xffffffffu, acc.y, 16);
    acc.z += __shfl_xor_sync(0xffffffffu, acc.z, 16);
    acc.w += __shfl_xor_sync(0xffffffffu, acc.w, 16);

    float s = d_dis[v];
    if (half == 0) {
        float4 bb = *(const float4*)(b1 + li * 4);
        float p0 = s * acc.x + bb.x;
        float p1 = s * acc.y + bb.y;
        float p2 = s * acc.z + bb.z;
        float p3 = s * acc.w + bb.w;
        float4 h;
        h.x = p0 > 0.f ? p0 : expm1f(p0);
        h.y = p1 > 0.f ? p1 : expm1f(p1);
        h.z = p2 > 0.f ? p2 : expm1f(p2);
        h.w = p3 > 0.f ? p3 : expm1f(p3);
        *(float4*)&sh[warp][li * 4] = h;
    }
    __syncwarp();

    // GEMM2 for this node: out[o=lane] = sum_f h[f] * W2[f][o]
    float o_acc = 0.f;
#pragma unroll
    for (int f = 0; f < 64; f++) o_acc = fmaf(sh[warp][f], sW[f][lane], o_acc);
    float val = s * o_acc;
    d_g2[(size_t)v * OUTC + lane] = val;
    // fp16 shadow: even lanes pack (val, val_of_lane+1)
    float vnext = __shfl_down_sync(0xffffffffu, val, 1);
    if (!(lane & 1)) {
        __half2 h = __floats2half2_rn(val, vnext);
        d_g2h[(size_t)v * 16 + (lane >> 1)] = *(unsigned*)&h;
    }
}

// ---------------- agg2: 2 edges/warp, fp16 uint/lane gather + ELU + dot(Wc) -> out ----------------
__global__ __launch_bounds__(256) void k_agg2(const float* __restrict__ b2,
                                              const float* __restrict__ Wc,
                                              const float* __restrict__ bc,
                                              float* __restrict__ out) {
    int t = threadIdx.x;
    int warp = t >> 5;
    int lane = t & 31;
    int v = blockIdx.x * 8 + warp;
    if (v >= NN) return;

    int start = d_off[v];
    int cnt = d_cnt[v];
    int half = lane >> 4;
    int li = lane & 15;     // feature pair

    float2 acc = make_float2(0.f, 0.f);
    if (half == 0)
        acc = *(const float2*)(d_g2 + (size_t)v * OUTC + li * 2);  // fp32 self

    for (int base = 0; base < cnt; base += 32) {
        int nb = cnt - base; if (nb > 32) nb = 32;
        int er = (lane < nb) ? d_erow[start + base + lane] : 0;
        for (int j = 0; j < nb; j += 16) {
            unsigned g[8];
            bool pv[8];
#pragma unroll
            for (int u = 0; u < 8; u++) {
                int jj = j + 2 * u + half;
                int r = __shfl_sync(0xffffffffu, er, jj & 31);
                pv[u] = jj < nb;
                r = pv[u] ? r : v;
                g[u] = d_g2h[(size_t)r * 16 + li];
            }
#pragma unroll
            for (int u = 0; u < 8; u++)
                if (pv[u]) {
                    float2 f = __half22float2(*(__half2*)&g[u]);
                    acc.x += f.x; acc.y += f.y;
                }
        }
    }

    acc.x += __shfl_xor_sync(0xffffffffu, acc.x, 16);
    acc.y += __shfl_xor_sync(0xffffffffu, acc.y, 16);

    float p = 0.f;
    if (half == 0) {
        float s = d_dis[v];
        float pre0 = s * acc.x + b2[li * 2];
        float pre1 = s * acc.y + b2[li * 2 + 1];
        float h0 = pre0 > 0.f ? pre0 : expm1f(pre0);
        float h1 = pre1 > 0.f ? pre1 : expm1f(pre1);
        p = h0 * Wc[li * 2] + h1 * Wc[li * 2 + 1];
    }
#pragma unroll
    for (int off = 16; off; off >>= 1) p += __shfl_xor_sync(0xffffffffu, p, off);
    if (lane == 0) out[v] = p + bc[0];
}

// ---------------- launch ----------------
extern "C" void kernel_launch(void* const* d_in, const int* in_sizes, int n_in,
                              void* d_out, int out_size) {
    const float* x  = (const float*)d_in[0];
    const void*  ei = d_in[1];                 // [2,E], int32 or int64 (auto-detected)
    const float* W1 = (const float*)d_in[2];
    const float* b1 = (const float*)d_in[3];
    const float* W2 = (const float*)d_in[4];
    const float* b2 = (const float*)d_in[5];
    const float* Wc = (const float*)d_in[6];
    const float* bc = (const float*)d_in[7];
    float*       out = (float*)d_out;

    k_zero<<<(NN + 255) / 256, 256>>>((const int*)ei);
    k_hist<<<(EE / 4 + 255) / 256, 256>>>(ei);
    k_bsum<<<NBLK, SCAN_B>>>();
    k_bscan<<<1, 128>>>();
    k_off<<<NBLK, SCAN_B>>>();
    k_fill<<<(EE / 4 + 255) / 256, 256>>>(ei);
    k_gemm1<<<(NN + 63) / 64, 128>>>(x, W1);
    k_agg1<<<(NN + 7) / 8, 256>>>(b1, W2);
    k_agg2<<<(NN + 7) / 8, 256>>>(b2, Wc, bc, out);
}